// round 15
// baseline (speedup 1.0000x reference)
#include <cuda_runtime.h>
#include <cuda_fp16.h>
#include <math.h>

// ---------------- problem constants (fixed by the dataset) ----------------
#define NODES 100000
#define FEAT  64
#define EDGES 800000
#define SAMP  25000
#define HID   128

// ---------------- scratch (device globals; no allocation) ----------------
__device__ float  d_q [(size_t)NODES * 128];   // W1^T x + b  (fp32)
__device__ __half d_pv[(size_t)NODES * 128];   // W2^T x      (fp16, hot random stream)
__device__ float  d_agg[(size_t)NODES * 128];  // per-node max-aggregated activations
__device__ int    d_cnt[NODES];                // hist counts (self-cleaning in scan1)
__device__ int    d_off[NODES + 1];            // exclusive offsets + sentinel
__device__ int    d_cur[NODES];
__device__ int    d_src[EDGES];
__device__ uint2  d_ppfu[EDGES];               // packed half4 ppf, edge order
__device__ uint2  d_ppf[EDGES];                // packed half4 ppf, sorted by target
__device__ int    d_bsum[128];
__device__ int    d_tlist[NODES];              // compact list of nodes with cnt>0
__device__ int    d_ntl;                       // its length (<= SAMP)

// ---------------- ppf + histogram (edge-parallel; runs on side stream) ----------------
__device__ __forceinline__ float angle3(float ax, float ay, float az,
                                        float bx, float by, float bz) {
    float cx = ay * bz - az * by;
    float cy = az * bx - ax * bz;
    float cz = ax * by - ay * bx;
    float cn = sqrtf(cx * cx + cy * cy + cz * cz);
    float d = ax * bx + ay * by + az * bz;
    return atan2f(cn, d);
}

__global__ void k_ppf(const int* __restrict__ col, const int* __restrict__ row,
                      const float* __restrict__ pos, const float* __restrict__ nor,
                      int E) {
    int i = blockIdx.x * blockDim.x + threadIdx.x;
    if (i >= E) return;
    int t = row[i];
    int s = col[i];
    atomicAdd(&d_cnt[t], 1);                         // fused histogram
    float px = pos[3 * s]     - pos[3 * t];
    float py = pos[3 * s + 1] - pos[3 * t + 1];
    float pz = pos[3 * s + 2] - pos[3 * t + 2];
    float nsx = nor[3 * s], nsy = nor[3 * s + 1], nsz = nor[3 * s + 2];
    float ntx = nor[3 * t], nty = nor[3 * t + 1], ntz = nor[3 * t + 2];
    float f0 = sqrtf(px * px + py * py + pz * pz);
    float f1 = angle3(ntx, nty, ntz, px, py, pz);    // angle(n1, pseudo)
    float f2 = angle3(nsx, nsy, nsz, px, py, pz);    // angle(n0, pseudo)
    float f3 = angle3(ntx, nty, ntz, nsx, nsy, nsz); // angle(n1, n0)
    __half2 h01 = __floats2half2_rn(f0, f1);
    __half2 h23 = __floats2half2_rn(f2, f3);
    d_ppfu[i] = make_uint2(*(unsigned*)&h01, *(unsigned*)&h23);
}

// ---------------- scan stage 1: per-1024-block inclusive scan; zero cnt after read ----
__global__ void k_scan1(int n) {
    __shared__ int sm[1024];
    int i = blockIdx.x * 1024 + threadIdx.x;
    int v = 0;
    if (i < n) {
        v = d_cnt[i];
        d_cnt[i] = 0;                  // self-clean for next replay (sole reader)
    }
    sm[threadIdx.x] = v;
    __syncthreads();
    for (int d = 1; d < 1024; d <<= 1) {
        int t = 0;
        if (threadIdx.x >= d) t = sm[threadIdx.x - d];
        __syncthreads();
        if (threadIdx.x >= d) sm[threadIdx.x] += t;
        __syncthreads();
    }
    if (i < n) d_off[i] = sm[threadIdx.x];            // block-local inclusive
    if (threadIdx.x == 1023) d_bsum[blockIdx.x] = sm[1023];
    if (i == 0) d_ntl = 0;
}

// ---------------- scan stage 2 (fused): finalize offsets + cursor + tlist -------------
__global__ void k_scan3(int n) {
    __shared__ int base_sm;
    int b = blockIdx.x;
    int tid = threadIdx.x;
    if (tid < 32) {                    // warp-reduce prefix of block sums [0, b)
        int s = 0;
        for (int k = tid; k < b; k += 32) s += d_bsum[k];
#pragma unroll
        for (int o = 16; o; o >>= 1) s += __shfl_down_sync(0xffffffffu, s, o);
        if (tid == 0) base_sm = s;
    }
    __syncthreads();
    int base = base_sm;
    int i = b * 1024 + tid;
    int inc = 0, prev = 0;
    if (i < n) {
        inc = d_off[i];
        prev = (tid == 0) ? 0 : d_off[i - 1];   // in-block read (written by scan1)
    }
    __syncthreads();                   // all reads of scan1's d_off done before writes
    if (i < n) {
        int c = inc - prev;            // this node's count
        int e = prev + base;           // global exclusive offset
        d_off[i] = e;
        d_cur[i] = e;
        if (c > 0) {                   // warp-uniform address -> REDUX-aggregated
            int p = atomicAdd(&d_ntl, 1);
            d_tlist[p] = i;
        }
    }
    if (i == 0) d_off[n] = EDGES;      // sentinel
}

// ---------------- scatter: pure permutation (ppf precomputed) -------------------------
__global__ void k_scatter(const int* __restrict__ col, const int* __restrict__ row, int E) {
    int i = blockIdx.x * blockDim.x + threadIdx.x;
    if (i < E) {
        int t = row[i];
        int p = atomicAdd(&d_cur[t], 1);
        d_src[p] = col[i];
        d_ppf[p] = d_ppfu[i];
    }
}

// ---------------- fused tf32 tensor-core GEMM: [64-row tile, K=64] x [64, 256] --------
// B[k][j] = (j<128) ? W[k][j] : W[64+k][j-128].
// cols 0..127 -> d_q (fp32, +bias), cols 128..255 -> d_pv (fp16).
#define A_STRIDE 68
#define B_STRIDE 264
#define GEMM_SMEM ((64 * A_STRIDE + 64 * B_STRIDE) * 4)

__device__ __forceinline__ unsigned tf32r(float f) {
    unsigned u;
    asm("cvt.rna.tf32.f32 %0, %1;" : "=r"(u) : "f"(f));
    return u;
}

__device__ __forceinline__ void mma_tf32(float& c0, float& c1, float& c2, float& c3,
                                         unsigned a0, unsigned a1, unsigned a2, unsigned a3,
                                         unsigned b0, unsigned b1) {
    asm volatile(
        "mma.sync.aligned.m16n8k8.row.col.f32.tf32.tf32.f32 "
        "{%0,%1,%2,%3}, {%4,%5,%6,%7}, {%8,%9}, {%0,%1,%2,%3};"
        : "+f"(c0), "+f"(c1), "+f"(c2), "+f"(c3)
        : "r"(a0), "r"(a1), "r"(a2), "r"(a3), "r"(b0), "r"(b1));
}

__global__ void __launch_bounds__(256)
k_gemm(const float* __restrict__ x, const float* __restrict__ Wm,
       const float* __restrict__ bv, int N) {
    extern __shared__ unsigned smem[];
    unsigned* As = smem;                     // [64][A_STRIDE]
    unsigned* Bs = smem + 64 * A_STRIDE;     // [64][B_STRIDE]
    int tid = threadIdx.x;
    int blk_row0 = blockIdx.x * 64;

    {   // A tile: 64 rows x 64 feats, tf32-rounded, row-major
        int r = tid >> 2;
        bool ok = (blk_row0 + r) < N;
        const float* xp = x + (size_t)(blk_row0 + r) * FEAT;
#pragma unroll
        for (int i = 0; i < 4; i++) {
            int c = (tid & 3) * 16 + i * 4;
            float4 v = ok ? *(const float4*)(xp + c) : make_float4(0.f, 0.f, 0.f, 0.f);
            unsigned* dst = &As[r * A_STRIDE + c];
            dst[0] = tf32r(v.x); dst[1] = tf32r(v.y);
            dst[2] = tf32r(v.z); dst[3] = tf32r(v.w);
        }
    }
    {   // B tile: 64 x 256 assembled from W rows [0:64) and [64:128)
#pragma unroll
        for (int it = 0; it < 16; it++) {
            int v = tid + 256 * it;          // 0..4095 float4 slots
            int k = v >> 6;
            int j0 = (v & 63) * 4;
            const float* src = (j0 < 128) ? (Wm + k * 128 + j0)
                                          : (Wm + (64 + k) * 128 + (j0 - 128));
            float4 w4 = *(const float4*)src;
            unsigned* dst = &Bs[k * B_STRIDE + j0];
            dst[0] = tf32r(w4.x); dst[1] = tf32r(w4.y);
            dst[2] = tf32r(w4.z); dst[3] = tf32r(w4.w);
        }
    }
    __syncthreads();

    int wid = tid >> 5;
    int lane = tid & 31;
    int row0 = (wid >> 2) * 32;      // 0 or 32
    int col0 = (wid & 3) * 64;       // 0,64,128,192
    int lr = lane >> 2;              // 0..7
    int lc = lane & 3;               // 0..3

    float c[2][8][4];
#pragma unroll
    for (int mt = 0; mt < 2; mt++)
#pragma unroll
        for (int nt = 0; nt < 8; nt++)
#pragma unroll
            for (int e = 0; e < 4; e++) c[mt][nt][e] = 0.f;

#pragma unroll
    for (int k0 = 0; k0 < 64; k0 += 8) {
        unsigned a[2][4], b[8][2];
#pragma unroll
        for (int mt = 0; mt < 2; mt++) {
            int ra = row0 + mt * 16 + lr;
            a[mt][0] = As[ra * A_STRIDE + k0 + lc];
            a[mt][1] = As[(ra + 8) * A_STRIDE + k0 + lc];
            a[mt][2] = As[ra * A_STRIDE + k0 + lc + 4];
            a[mt][3] = As[(ra + 8) * A_STRIDE + k0 + lc + 4];
        }
#pragma unroll
        for (int nt = 0; nt < 8; nt++) {
            int cb = col0 + nt * 8 + lr;
            b[nt][0] = Bs[(k0 + lc) * B_STRIDE + cb];
            b[nt][1] = Bs[(k0 + lc + 4) * B_STRIDE + cb];
        }
#pragma unroll
        for (int mt = 0; mt < 2; mt++)
#pragma unroll
            for (int nt = 0; nt < 8; nt++)
                mma_tf32(c[mt][nt][0], c[mt][nt][1], c[mt][nt][2], c[mt][nt][3],
                         a[mt][0], a[mt][1], a[mt][2], a[mt][3],
                         b[nt][0], b[nt][1]);
    }

    bool is_q = (col0 < 128);
#pragma unroll
    for (int mt = 0; mt < 2; mt++) {
        int r_lo = blk_row0 + row0 + mt * 16 + lr;
        int r_hi = r_lo + 8;
#pragma unroll
        for (int nt = 0; nt < 8; nt++) {
            int cc = col0 + nt * 8 + 2 * lc;
            if (is_q) {
                float2 bb = *(const float2*)&bv[cc];
                if (r_lo < N)
                    *(float2*)&d_q[(size_t)r_lo * 128 + cc] =
                        make_float2(c[mt][nt][0] + bb.x, c[mt][nt][1] + bb.y);
                if (r_hi < N)
                    *(float2*)&d_q[(size_t)r_hi * 128 + cc] =
                        make_float2(c[mt][nt][2] + bb.x, c[mt][nt][3] + bb.y);
            } else {
                int cp = cc - 128;
                if (r_lo < N) {
                    __half2 h = __floats2half2_rn(c[mt][nt][0], c[mt][nt][1]);
                    *(unsigned*)&d_pv[(size_t)r_lo * 128 + cp] = *(unsigned*)&h;
                }
                if (r_hi < N) {
                    __half2 h = __floats2half2_rn(c[mt][nt][2], c[mt][nt][3]);
                    *(unsigned*)&d_pv[(size_t)r_hi * 128 + cp] = *(unsigned*)&h;
                }
            }
        }
    }
}

// ---------------- edge aggregation: one warp per ACTIVE target, 8-edge batches --------
__global__ void k_agg(const float* __restrict__ Wm) {
    int wg = (blockIdx.x * blockDim.x + threadIdx.x) >> 5;
    if (wg >= d_ntl) return;
    int w = d_tlist[wg];                 // cnt > 0 guaranteed
    int lane = threadIdx.x & 31;
    int start = d_off[w];
    int end = d_off[w + 1];
    int col = lane * 4;

    float4 w0f = *(const float4*)&Wm[128 * 128 + col];   // ppf weight rows
    float4 w1f = *(const float4*)&Wm[129 * 128 + col];
    float4 w2f = *(const float4*)&Wm[130 * 128 + col];
    float4 w3f = *(const float4*)&Wm[131 * 128 + col];
    __half2 w0a = __floats2half2_rn(w0f.x, w0f.y), w0b = __floats2half2_rn(w0f.z, w0f.w);
    __half2 w1a = __floats2half2_rn(w1f.x, w1f.y), w1b = __floats2half2_rn(w1f.z, w1f.w);
    __half2 w2a = __floats2half2_rn(w2f.x, w2f.y), w2b = __floats2half2_rn(w2f.z, w2f.w);
    __half2 w3a = __floats2half2_rn(w3f.x, w3f.y), w3b = __floats2half2_rn(w3f.z, w3f.w);

    const __half2 NEGINF = __half2half2(__ushort_as_half(0xFC00));
    __half2 m0 = NEGINF, m1 = NEGINF;

    for (int base = start; base < end; base += 32) {
        int j = base + lane;
        int s = 0;
        uint2 pf = make_uint2(0u, 0u);
        if (j < end) {
            s = d_src[j];           // coalesced
            pf = d_ppf[j];          // coalesced 8B
        }
        int c32 = end - base;
        if (c32 > 32) c32 = 32;
        int i = 0;
        // ---- 8-edge batches: shfl+LDG issued up front (MLP=8), then HFMA2 block ----
        for (; i + 8 <= c32; i += 8) {
            uint2 pvv[8];
            unsigned gx[8], gy[8];
#pragma unroll
            for (int u = 0; u < 8; u++) {
                int si = __shfl_sync(0xffffffffu, s, i + u);
                gx[u] = __shfl_sync(0xffffffffu, pf.x, i + u);
                gy[u] = __shfl_sync(0xffffffffu, pf.y, i + u);
                pvv[u] = *(const uint2*)&d_pv[(size_t)si * 128 + col];
            }
            __half2 z0[8], z1[8];
#pragma unroll
            for (int u = 0; u < 8; u++) {
                __half2 hx = *(__half2*)&gx[u];       // (f0, f1)
                __half2 hy = *(__half2*)&gy[u];       // (f2, f3)
                __half2 g0 = __low2half2(hx),  g1 = __high2half2(hx);
                __half2 g2 = __low2half2(hy),  g3 = __high2half2(hy);
                __half2 p01 = *(__half2*)&pvv[u].x;
                __half2 p23 = *(__half2*)&pvv[u].y;
                z0[u] = __hfma2(g0, w0a, p01);  z1[u] = __hfma2(g0, w0b, p23);
                z0[u] = __hfma2(g1, w1a, z0[u]); z1[u] = __hfma2(g1, w1b, z1[u]);
                z0[u] = __hfma2(g2, w2a, z0[u]); z1[u] = __hfma2(g2, w2b, z1[u]);
                z0[u] = __hfma2(g3, w3a, z0[u]); z1[u] = __hfma2(g3, w3b, z1[u]);
            }
            __half2 t0 = __hmax2(__hmax2(__hmax2(z0[0], z0[1]), __hmax2(z0[2], z0[3])),
                                 __hmax2(__hmax2(z0[4], z0[5]), __hmax2(z0[6], z0[7])));
            __half2 t1 = __hmax2(__hmax2(__hmax2(z1[0], z1[1]), __hmax2(z1[2], z1[3])),
                                 __hmax2(__hmax2(z1[4], z1[5]), __hmax2(z1[6], z1[7])));
            m0 = __hmax2(m0, t0);
            m1 = __hmax2(m1, t1);
        }
        // ---- remainder ----
        for (; i < c32; i++) {
            int si = __shfl_sync(0xffffffffu, s, i);
            unsigned hxu = __shfl_sync(0xffffffffu, pf.x, i);
            unsigned hyu = __shfl_sync(0xffffffffu, pf.y, i);
            uint2 hv = *(const uint2*)&d_pv[(size_t)si * 128 + col];
            __half2 hx = *(__half2*)&hxu;
            __half2 hy = *(__half2*)&hyu;
            __half2 g0 = __low2half2(hx),  g1 = __high2half2(hx);
            __half2 g2 = __low2half2(hy),  g3 = __high2half2(hy);
            __half2 p01 = *(__half2*)&hv.x;
            __half2 p23 = *(__half2*)&hv.y;
            __half2 z0 = __hfma2(g0, w0a, p01);
            __half2 z1 = __hfma2(g0, w0b, p23);
            z0 = __hfma2(g1, w1a, z0); z1 = __hfma2(g1, w1b, z1);
            z0 = __hfma2(g2, w2a, z0); z1 = __hfma2(g2, w2b, z1);
            z0 = __hfma2(g3, w3a, z0); z1 = __hfma2(g3, w3b, z1);
            m0 = __hmax2(m0, z0);
            m1 = __hmax2(m1, z1);
        }
    }
    float2 a = __half22float2(m0);
    float2 b = __half22float2(m1);
    float4 q = *(const float4*)&d_q[(size_t)w * 128 + col];
    float4 r;
    r.x = fmaxf(q.x + a.x, 0.f);
    r.y = fmaxf(q.y + a.y, 0.f);
    r.z = fmaxf(q.z + b.x, 0.f);
    r.w = fmaxf(q.w + b.y, 0.f);
    *(float4*)&d_agg[(size_t)w * 128 + col] = r;
}

// ---------------- gather: out[s] = agg[idx[s]] (0 if no edges), pos_out ----------------
__global__ void k_gather(const float* __restrict__ pos, const int* __restrict__ idx,
                         float* __restrict__ out, int S) {
    int s = blockIdx.x;
    int h = threadIdx.x;  // 128
    int t = idx[s];
    bool has = d_off[t + 1] > d_off[t];
    float v = has ? d_agg[(size_t)t * 128 + h] : 0.f;
    out[(size_t)s * 128 + h] = v;
    if (h < 3) out[(size_t)S * 128 + (size_t)s * 3 + h] = pos[3 * t + h];
}

// ---------------- launch: sB: ppf+hist  ||  main: gemm -> scans -> scatter -> agg -----
extern "C" void kernel_launch(void* const* d_in, const int* in_sizes, int n_in,
                              void* d_out, int out_size) {
    const float *x = 0, *pos = 0, *nor = 0, *Wm = 0, *bv = 0;
    const int *edge = 0, *idx = 0;
    for (int i = 0; i < n_in; i++) {
        int sz = in_sizes[i];
        if (sz == NODES * FEAT) x = (const float*)d_in[i];
        else if (sz == NODES * 3) { if (!pos) pos = (const float*)d_in[i]; else nor = (const float*)d_in[i]; }
        else if (sz == (2 * FEAT + 4) * HID) Wm = (const float*)d_in[i];
        else if (sz == HID) bv = (const float*)d_in[i];
        else if (sz == 2 * EDGES) edge = (const int*)d_in[i];
        else if (sz == SAMP) idx = (const int*)d_in[i];
    }
    const int* ecol = edge;          // e0 (sources)
    const int* erow = edge + EDGES;  // e1 (targets)

    static cudaStream_t sB = 0;
    static cudaEvent_t eFork = 0, ePpf = 0;
    if (!sB) {
        cudaStreamCreateWithFlags(&sB, cudaStreamNonBlocking);
        cudaEventCreateWithFlags(&eFork, cudaEventDisableTiming);
        cudaEventCreateWithFlags(&ePpf,  cudaEventDisableTiming);
        cudaFuncSetAttribute(k_gemm, cudaFuncAttributeMaxDynamicSharedMemorySize, GEMM_SMEM);
    }

    // fork: ppf + fused histogram on side stream
    cudaEventRecord(eFork, 0);
    cudaStreamWaitEvent(sB, eFork, 0);
    k_ppf<<<(EDGES + 255) / 256, 256, 0, sB>>>(ecol, erow, pos, nor, EDGES);
    cudaEventRecord(ePpf, sB);

    // main: gemm overlaps ppf, then the dependent chain
    k_gemm<<<(NODES + 63) / 64, 256, GEMM_SMEM>>>(x, Wm, bv, NODES);
    cudaStreamWaitEvent(0, ePpf, 0);                      // scan needs counts; scatter needs ppfu
    k_scan1<<<(NODES + 1023) / 1024, 1024>>>(NODES);
    k_scan3<<<(NODES + 1023) / 1024, 1024>>>(NODES);
    k_scatter<<<(EDGES + 255) / 256, 256>>>(ecol, erow, EDGES);
    k_agg<<<(SAMP + 7) / 8, 256>>>(Wm);
    k_gather<<<SAMP, 128>>>(pos, idx, (float*)d_out, SAMP);
}

// round 16
// speedup vs baseline: 1.0380x; 1.0380x over previous
#include <cuda_runtime.h>
#include <cuda_fp16.h>
#include <math.h>

// ---------------- problem constants (fixed by the dataset) ----------------
#define NODES 100000
#define FEAT  64
#define EDGES 800000
#define SAMP  25000
#define HID   128

// ---------------- scratch (device globals; no allocation) ----------------
__device__ float  d_q [(size_t)NODES * 128];   // W1^T x + b  (fp32)
__device__ __half d_pv[(size_t)NODES * 128];   // W2^T x      (fp16, hot random stream)
__device__ float  d_agg[(size_t)NODES * 128];  // per-node max-aggregated activations
__device__ int    d_cnt[NODES];
__device__ int    d_off[NODES];
__device__ int    d_cur[NODES];
__device__ int    d_src[EDGES];
__device__ uint2  d_ppfu[EDGES];               // packed half4 ppf, edge order
__device__ uint2  d_ppf[EDGES];                // packed half4 ppf, sorted by target
__device__ int    d_bsum[128];
__device__ int    d_tlist[NODES];              // compact list of nodes with cnt>0
__device__ int    d_ntl;                       // its length (<= SAMP)

// ---------------- counting sort of edges by target node ----------------
__global__ void k_zero_cnt(int n) {
    int i = blockIdx.x * blockDim.x + threadIdx.x;
    if (i < n) d_cnt[i] = 0;
    if (i == 0) d_ntl = 0;
}

__global__ void k_hist(const int* __restrict__ row, int E) {
    int i = blockIdx.x * blockDim.x + threadIdx.x;
    if (i < E) atomicAdd(&d_cnt[row[i]], 1);
}

__global__ void k_scan1(int n) {  // per-1024-block inclusive scan, block sums out
    __shared__ int sm[1024];
    int i = blockIdx.x * 1024 + threadIdx.x;
    int v = (i < n) ? d_cnt[i] : 0;
    sm[threadIdx.x] = v;
    __syncthreads();
    for (int d = 1; d < 1024; d <<= 1) {
        int t = 0;
        if (threadIdx.x >= d) t = sm[threadIdx.x - d];
        __syncthreads();
        if (threadIdx.x >= d) sm[threadIdx.x] += t;
        __syncthreads();
    }
    if (i < n) d_off[i] = sm[threadIdx.x];            // inclusive for now
    if (threadIdx.x == 1023) d_bsum[blockIdx.x] = sm[1023];
}

// fused (old scan2+scan3): per-block prefix of bsum via warp reduce, finalize, tlist
__global__ void k_scan3(int n) {
    __shared__ int base_sm;
    int b = blockIdx.x;
    int tid = threadIdx.x;
    if (tid < 32) {                    // prefix sum of d_bsum[0..b)
        int s = 0;
        for (int k = tid; k < b; k += 32) s += d_bsum[k];
#pragma unroll
        for (int o = 16; o; o >>= 1) s += __shfl_down_sync(0xffffffffu, s, o);
        if (tid == 0) base_sm = s;
    }
    __syncthreads();
    int base = base_sm;
    int i = b * 1024 + tid;
    if (i < n) {
        int c = d_cnt[i];
        int e = d_off[i] - c + base;   // inclusive -> exclusive + global base
        d_off[i] = e;
        d_cur[i] = e;
        if (c > 0) {                   // warp-uniform address -> REDUX-aggregated
            int p = atomicAdd(&d_ntl, 1);
            d_tlist[p] = i;
        }
    }
}

// ---------------- ppf compute (edge-parallel, unsorted; runs on side stream) ---------
__device__ __forceinline__ float angle3(float ax, float ay, float az,
                                        float bx, float by, float bz) {
    float cx = ay * bz - az * by;
    float cy = az * bx - ax * bz;
    float cz = ax * by - ay * bx;
    float cn = sqrtf(cx * cx + cy * cy + cz * cz);
    float d = ax * bx + ay * by + az * bz;
    return atan2f(cn, d);
}

__global__ void k_ppf(const int* __restrict__ col, const int* __restrict__ row,
                      const float* __restrict__ pos, const float* __restrict__ nor,
                      int E) {
    int i = blockIdx.x * blockDim.x + threadIdx.x;
    if (i >= E) return;
    int t = row[i];
    int s = col[i];
    float px = pos[3 * s]     - pos[3 * t];
    float py = pos[3 * s + 1] - pos[3 * t + 1];
    float pz = pos[3 * s + 2] - pos[3 * t + 2];
    float nsx = nor[3 * s], nsy = nor[3 * s + 1], nsz = nor[3 * s + 2];
    float ntx = nor[3 * t], nty = nor[3 * t + 1], ntz = nor[3 * t + 2];
    float f0 = sqrtf(px * px + py * py + pz * pz);
    float f1 = angle3(ntx, nty, ntz, px, py, pz);    // angle(n1, pseudo)
    float f2 = angle3(nsx, nsy, nsz, px, py, pz);    // angle(n0, pseudo)
    float f3 = angle3(ntx, nty, ntz, nsx, nsy, nsz); // angle(n1, n0)
    __half2 h01 = __floats2half2_rn(f0, f1);
    __half2 h23 = __floats2half2_rn(f2, f3);
    d_ppfu[i] = make_uint2(*(unsigned*)&h01, *(unsigned*)&h23);
}

// ---------------- scatter: pure permutation (ppf precomputed) -------------------------
__global__ void k_scatter(const int* __restrict__ col, const int* __restrict__ row, int E) {
    int i = blockIdx.x * blockDim.x + threadIdx.x;
    if (i < E) {
        int t = row[i];
        int p = atomicAdd(&d_cur[t], 1);
        d_src[p] = col[i];
        d_ppf[p] = d_ppfu[i];
    }
}

// ---------------- fused tf32 tensor-core GEMM: [64-row tile, K=64] x [64, 256] --------
// B[k][j] = (j<128) ? W[k][j] : W[64+k][j-128].
// cols 0..127 -> d_q (fp32, +bias), cols 128..255 -> d_pv (fp16).
#define A_STRIDE 68
#define B_STRIDE 264
#define GEMM_SMEM ((64 * A_STRIDE + 64 * B_STRIDE) * 4)

__device__ __forceinline__ unsigned tf32r(float f) {
    unsigned u;
    asm("cvt.rna.tf32.f32 %0, %1;" : "=r"(u) : "f"(f));
    return u;
}

__device__ __forceinline__ void mma_tf32(float& c0, float& c1, float& c2, float& c3,
                                         unsigned a0, unsigned a1, unsigned a2, unsigned a3,
                                         unsigned b0, unsigned b1) {
    asm volatile(
        "mma.sync.aligned.m16n8k8.row.col.f32.tf32.tf32.f32 "
        "{%0,%1,%2,%3}, {%4,%5,%6,%7}, {%8,%9}, {%0,%1,%2,%3};"
        : "+f"(c0), "+f"(c1), "+f"(c2), "+f"(c3)
        : "r"(a0), "r"(a1), "r"(a2), "r"(a3), "r"(b0), "r"(b1));
}

__global__ void __launch_bounds__(256)
k_gemm(const float* __restrict__ x, const float* __restrict__ Wm,
       const float* __restrict__ bv, int N) {
    extern __shared__ unsigned smem[];
    unsigned* As = smem;                     // [64][A_STRIDE]
    unsigned* Bs = smem + 64 * A_STRIDE;     // [64][B_STRIDE]
    int tid = threadIdx.x;
    int blk_row0 = blockIdx.x * 64;

    {   // A tile: 64 rows x 64 feats, tf32-rounded, row-major
        int r = tid >> 2;
        bool ok = (blk_row0 + r) < N;
        const float* xp = x + (size_t)(blk_row0 + r) * FEAT;
#pragma unroll
        for (int i = 0; i < 4; i++) {
            int c = (tid & 3) * 16 + i * 4;
            float4 v = ok ? *(const float4*)(xp + c) : make_float4(0.f, 0.f, 0.f, 0.f);
            unsigned* dst = &As[r * A_STRIDE + c];
            dst[0] = tf32r(v.x); dst[1] = tf32r(v.y);
            dst[2] = tf32r(v.z); dst[3] = tf32r(v.w);
        }
    }
    {   // B tile: 64 x 256 assembled from W rows [0:64) and [64:128)
#pragma unroll
        for (int it = 0; it < 16; it++) {
            int v = tid + 256 * it;          // 0..4095 float4 slots
            int k = v >> 6;
            int j0 = (v & 63) * 4;
            const float* src = (j0 < 128) ? (Wm + k * 128 + j0)
                                          : (Wm + (64 + k) * 128 + (j0 - 128));
            float4 w4 = *(const float4*)src;
            unsigned* dst = &Bs[k * B_STRIDE + j0];
            dst[0] = tf32r(w4.x); dst[1] = tf32r(w4.y);
            dst[2] = tf32r(w4.z); dst[3] = tf32r(w4.w);
        }
    }
    __syncthreads();

    int wid = tid >> 5;
    int lane = tid & 31;
    int row0 = (wid >> 2) * 32;      // 0 or 32
    int col0 = (wid & 3) * 64;       // 0,64,128,192
    int lr = lane >> 2;              // 0..7
    int lc = lane & 3;               // 0..3

    float c[2][8][4];
#pragma unroll
    for (int mt = 0; mt < 2; mt++)
#pragma unroll
        for (int nt = 0; nt < 8; nt++)
#pragma unroll
            for (int e = 0; e < 4; e++) c[mt][nt][e] = 0.f;

#pragma unroll
    for (int k0 = 0; k0 < 64; k0 += 8) {
        unsigned a[2][4], b[8][2];
#pragma unroll
        for (int mt = 0; mt < 2; mt++) {
            int ra = row0 + mt * 16 + lr;
            a[mt][0] = As[ra * A_STRIDE + k0 + lc];
            a[mt][1] = As[(ra + 8) * A_STRIDE + k0 + lc];
            a[mt][2] = As[ra * A_STRIDE + k0 + lc + 4];
            a[mt][3] = As[(ra + 8) * A_STRIDE + k0 + lc + 4];
        }
#pragma unroll
        for (int nt = 0; nt < 8; nt++) {
            int cb = col0 + nt * 8 + lr;
            b[nt][0] = Bs[(k0 + lc) * B_STRIDE + cb];
            b[nt][1] = Bs[(k0 + lc + 4) * B_STRIDE + cb];
        }
#pragma unroll
        for (int mt = 0; mt < 2; mt++)
#pragma unroll
            for (int nt = 0; nt < 8; nt++)
                mma_tf32(c[mt][nt][0], c[mt][nt][1], c[mt][nt][2], c[mt][nt][3],
                         a[mt][0], a[mt][1], a[mt][2], a[mt][3],
                         b[nt][0], b[nt][1]);
    }

    bool is_q = (col0 < 128);
#pragma unroll
    for (int mt = 0; mt < 2; mt++) {
        int r_lo = blk_row0 + row0 + mt * 16 + lr;
        int r_hi = r_lo + 8;
#pragma unroll
        for (int nt = 0; nt < 8; nt++) {
            int cc = col0 + nt * 8 + 2 * lc;
            if (is_q) {
                float2 bb = *(const float2*)&bv[cc];
                if (r_lo < N)
                    *(float2*)&d_q[(size_t)r_lo * 128 + cc] =
                        make_float2(c[mt][nt][0] + bb.x, c[mt][nt][1] + bb.y);
                if (r_hi < N)
                    *(float2*)&d_q[(size_t)r_hi * 128 + cc] =
                        make_float2(c[mt][nt][2] + bb.x, c[mt][nt][3] + bb.y);
            } else {
                int cp = cc - 128;
                if (r_lo < N) {
                    __half2 h = __floats2half2_rn(c[mt][nt][0], c[mt][nt][1]);
                    *(unsigned*)&d_pv[(size_t)r_lo * 128 + cp] = *(unsigned*)&h;
                }
                if (r_hi < N) {
                    __half2 h = __floats2half2_rn(c[mt][nt][2], c[mt][nt][3]);
                    *(unsigned*)&d_pv[(size_t)r_hi * 128 + cp] = *(unsigned*)&h;
                }
            }
        }
    }
}

// ---------------- edge aggregation: one warp per ACTIVE target, 8-edge batches --------
__global__ void k_agg(const float* __restrict__ Wm) {
    int wg = (blockIdx.x * blockDim.x + threadIdx.x) >> 5;
    if (wg >= d_ntl) return;
    int w = d_tlist[wg];                 // cnt > 0 guaranteed
    int cnt = d_cnt[w];
    int lane = threadIdx.x & 31;
    int start = d_off[w];
    int end = start + cnt;
    int col = lane * 4;

    float4 w0f = *(const float4*)&Wm[128 * 128 + col];   // ppf weight rows
    float4 w1f = *(const float4*)&Wm[129 * 128 + col];
    float4 w2f = *(const float4*)&Wm[130 * 128 + col];
    float4 w3f = *(const float4*)&Wm[131 * 128 + col];
    __half2 w0a = __floats2half2_rn(w0f.x, w0f.y), w0b = __floats2half2_rn(w0f.z, w0f.w);
    __half2 w1a = __floats2half2_rn(w1f.x, w1f.y), w1b = __floats2half2_rn(w1f.z, w1f.w);
    __half2 w2a = __floats2half2_rn(w2f.x, w2f.y), w2b = __floats2half2_rn(w2f.z, w2f.w);
    __half2 w3a = __floats2half2_rn(w3f.x, w3f.y), w3b = __floats2half2_rn(w3f.z, w3f.w);

    const __half2 NEGINF = __half2half2(__ushort_as_half(0xFC00));
    __half2 m0 = NEGINF, m1 = NEGINF;

    for (int base = start; base < end; base += 32) {
        int j = base + lane;
        int s = 0;
        uint2 pf = make_uint2(0u, 0u);
        if (j < end) {
            s = d_src[j];           // coalesced
            pf = d_ppf[j];          // coalesced 8B
        }
        int c32 = end - base;
        if (c32 > 32) c32 = 32;
        int i = 0;
        // ---- 8-edge batches: shfl+LDG issued up front (MLP=8), then HFMA2 block ----
        for (; i + 8 <= c32; i += 8) {
            uint2 pvv[8];
            unsigned gx[8], gy[8];
#pragma unroll
            for (int u = 0; u < 8; u++) {
                int si = __shfl_sync(0xffffffffu, s, i + u);
                gx[u] = __shfl_sync(0xffffffffu, pf.x, i + u);
                gy[u] = __shfl_sync(0xffffffffu, pf.y, i + u);
                pvv[u] = *(const uint2*)&d_pv[(size_t)si * 128 + col];
            }
            __half2 z0[8], z1[8];
#pragma unroll
            for (int u = 0; u < 8; u++) {
                __half2 hx = *(__half2*)&gx[u];       // (f0, f1)
                __half2 hy = *(__half2*)&gy[u];       // (f2, f3)
                __half2 g0 = __low2half2(hx),  g1 = __high2half2(hx);
                __half2 g2 = __low2half2(hy),  g3 = __high2half2(hy);
                __half2 p01 = *(__half2*)&pvv[u].x;
                __half2 p23 = *(__half2*)&pvv[u].y;
                z0[u] = __hfma2(g0, w0a, p01);  z1[u] = __hfma2(g0, w0b, p23);
                z0[u] = __hfma2(g1, w1a, z0[u]); z1[u] = __hfma2(g1, w1b, z1[u]);
                z0[u] = __hfma2(g2, w2a, z0[u]); z1[u] = __hfma2(g2, w2b, z1[u]);
                z0[u] = __hfma2(g3, w3a, z0[u]); z1[u] = __hfma2(g3, w3b, z1[u]);
            }
            __half2 t0 = __hmax2(__hmax2(__hmax2(z0[0], z0[1]), __hmax2(z0[2], z0[3])),
                                 __hmax2(__hmax2(z0[4], z0[5]), __hmax2(z0[6], z0[7])));
            __half2 t1 = __hmax2(__hmax2(__hmax2(z1[0], z1[1]), __hmax2(z1[2], z1[3])),
                                 __hmax2(__hmax2(z1[4], z1[5]), __hmax2(z1[6], z1[7])));
            m0 = __hmax2(m0, t0);
            m1 = __hmax2(m1, t1);
        }
        // ---- remainder ----
        for (; i < c32; i++) {
            int si = __shfl_sync(0xffffffffu, s, i);
            unsigned hxu = __shfl_sync(0xffffffffu, pf.x, i);
            unsigned hyu = __shfl_sync(0xffffffffu, pf.y, i);
            uint2 hv = *(const uint2*)&d_pv[(size_t)si * 128 + col];
            __half2 hx = *(__half2*)&hxu;
            __half2 hy = *(__half2*)&hyu;
            __half2 g0 = __low2half2(hx),  g1 = __high2half2(hx);
            __half2 g2 = __low2half2(hy),  g3 = __high2half2(hy);
            __half2 p01 = *(__half2*)&hv.x;
            __half2 p23 = *(__half2*)&hv.y;
            __half2 z0 = __hfma2(g0, w0a, p01);
            __half2 z1 = __hfma2(g0, w0b, p23);
            z0 = __hfma2(g1, w1a, z0); z1 = __hfma2(g1, w1b, z1);
            z0 = __hfma2(g2, w2a, z0); z1 = __hfma2(g2, w2b, z1);
            z0 = __hfma2(g3, w3a, z0); z1 = __hfma2(g3, w3b, z1);
            m0 = __hmax2(m0, z0);
            m1 = __hmax2(m1, z1);
        }
    }
    float2 a = __half22float2(m0);
    float2 b = __half22float2(m1);
    float4 q = *(const float4*)&d_q[(size_t)w * 128 + col];
    float4 r;
    r.x = fmaxf(q.x + a.x, 0.f);
    r.y = fmaxf(q.y + a.y, 0.f);
    r.z = fmaxf(q.z + b.x, 0.f);
    r.w = fmaxf(q.w + b.y, 0.f);
    *(float4*)&d_agg[(size_t)w * 128 + col] = r;
}

// ---------------- gather: out[s] = agg[idx[s]] (0 if no edges), pos_out ----------------
__global__ void k_gather(const float* __restrict__ pos, const int* __restrict__ idx,
                         float* __restrict__ out, int S) {
    int s = blockIdx.x;
    int h = threadIdx.x;  // 128
    int t = idx[s];
    float v = d_cnt[t] ? d_agg[(size_t)t * 128 + h] : 0.f;
    out[(size_t)s * 128 + h] = v;
    if (h < 3) out[(size_t)S * 128 + (size_t)s * 3 + h] = pos[3 * t + h];
}

// ---------------- launch (gemm+ppf on side stream || sort chain) ----------------------
extern "C" void kernel_launch(void* const* d_in, const int* in_sizes, int n_in,
                              void* d_out, int out_size) {
    const float *x = 0, *pos = 0, *nor = 0, *Wm = 0, *bv = 0;
    const int *edge = 0, *idx = 0;
    for (int i = 0; i < n_in; i++) {
        int sz = in_sizes[i];
        if (sz == NODES * FEAT) x = (const float*)d_in[i];
        else if (sz == NODES * 3) { if (!pos) pos = (const float*)d_in[i]; else nor = (const float*)d_in[i]; }
        else if (sz == (2 * FEAT + 4) * HID) Wm = (const float*)d_in[i];
        else if (sz == HID) bv = (const float*)d_in[i];
        else if (sz == 2 * EDGES) edge = (const int*)d_in[i];
        else if (sz == SAMP) idx = (const int*)d_in[i];
    }
    const int* ecol = edge;          // e0 (sources)
    const int* erow = edge + EDGES;  // e1 (targets)

    static cudaStream_t sB = 0;
    static cudaEvent_t eFork = 0, ePv = 0, ePpf = 0;
    if (!sB) {
        cudaStreamCreateWithFlags(&sB, cudaStreamNonBlocking);
        cudaEventCreateWithFlags(&eFork, cudaEventDisableTiming);
        cudaEventCreateWithFlags(&ePv,   cudaEventDisableTiming);
        cudaEventCreateWithFlags(&ePpf,  cudaEventDisableTiming);
        cudaFuncSetAttribute(k_gemm, cudaFuncAttributeMaxDynamicSharedMemorySize, GEMM_SMEM);
    }

    // fork: tensor-core gemm + ppf compute on sB, independent of the sort chain
    cudaEventRecord(eFork, 0);
    cudaStreamWaitEvent(sB, eFork, 0);
    k_gemm<<<(NODES + 63) / 64, 256, GEMM_SMEM, sB>>>(x, Wm, bv, NODES);
    cudaEventRecord(ePv, sB);
    k_ppf<<<(EDGES + 255) / 256, 256, 0, sB>>>(ecol, erow, pos, nor, EDGES);
    cudaEventRecord(ePpf, sB);

    // sort chain on the main stream
    k_zero_cnt<<<(NODES + 255) / 256, 256>>>(NODES);
    k_hist<<<(EDGES + 255) / 256, 256>>>(erow, EDGES);
    k_scan1<<<(NODES + 1023) / 1024, 1024>>>(NODES);
    k_scan3<<<(NODES + 1023) / 1024, 1024>>>(NODES);
    cudaStreamWaitEvent(0, ePpf, 0);   // scatter permutes d_ppfu
    k_scatter<<<(EDGES + 255) / 256, 256>>>(ecol, erow, EDGES);

    // join: agg needs scatter (main) + gemm (sB); one warp per active target
    cudaStreamWaitEvent(0, ePv, 0);
    k_agg<<<(SAMP + 7) / 8, 256>>>(Wm);
    k_gather<<<SAMP, 128>>>(pos, idx, (float*)d_out, SAMP);
}

// round 17
// speedup vs baseline: 1.0593x; 1.0205x over previous
#include <cuda_runtime.h>
#include <cuda_fp16.h>
#include <math.h>

// ---------------- problem constants (fixed by the dataset) ----------------
#define NODES 100000
#define FEAT  64
#define EDGES 800000
#define SAMP  25000
#define HID   128

// ---------------- scratch (device globals; no allocation) ----------------
__device__ float  d_q [(size_t)NODES * 128];   // W1^T x + b  (fp32)
__device__ __half d_pv[(size_t)NODES * 128];   // W2^T x      (fp16, hot random stream)
__device__ float  d_agg[(size_t)NODES * 128];  // per-node max-aggregated activations
__device__ int    d_cnt[NODES];                // hist counts (self-cleaned by scan1)
__device__ int    d_off[NODES + 1];            // exclusive offsets + sentinel
__device__ int    d_cur[NODES];
__device__ int    d_src[EDGES];
__device__ uint2  d_ppfu[EDGES];               // packed half4 ppf, edge order
__device__ uint2  d_ppf[EDGES];                // packed half4 ppf, sorted by target
__device__ int    d_bsum[128];
__device__ int    d_tlist[NODES];              // compact list of nodes with cnt>0
__device__ int    d_ntl;                       // its length (<= SAMP)

// ---------------- counting sort of edges by target node ----------------
__global__ void k_hist(const int* __restrict__ row, int E) {
    int i = blockIdx.x * blockDim.x + threadIdx.x;
    if (i < E) atomicAdd(&d_cnt[row[i]], 1);
}

// per-1024-block inclusive scan; zero cnt after read (sole consumer of d_cnt)
__global__ void k_scan1(int n) {
    __shared__ int sm[1024];
    int i = blockIdx.x * 1024 + threadIdx.x;
    int v = 0;
    if (i < n) {
        v = d_cnt[i];
        d_cnt[i] = 0;                  // self-clean for next graph replay
    }
    sm[threadIdx.x] = v;
    __syncthreads();
    for (int d = 1; d < 1024; d <<= 1) {
        int t = 0;
        if (threadIdx.x >= d) t = sm[threadIdx.x - d];
        __syncthreads();
        if (threadIdx.x >= d) sm[threadIdx.x] += t;
        __syncthreads();
    }
    if (i < n) d_off[i] = sm[threadIdx.x];            // block-local inclusive
    if (threadIdx.x == 1023) d_bsum[blockIdx.x] = sm[1023];
    if (i == 0) d_ntl = 0;
}

// fused scan2+scan3: per-block prefix of bsum (warp reduce), finalize, tlist, sentinel
__global__ void k_scan3(int n) {
    __shared__ int base_sm;
    int b = blockIdx.x;
    int tid = threadIdx.x;
    if (tid < 32) {                    // prefix sum of d_bsum[0..b)
        int s = 0;
        for (int k = tid; k < b; k += 32) s += d_bsum[k];
#pragma unroll
        for (int o = 16; o; o >>= 1) s += __shfl_down_sync(0xffffffffu, s, o);
        if (tid == 0) base_sm = s;
    }
    __syncthreads();
    int base = base_sm;
    int i = b * 1024 + tid;
    int inc = 0, prev = 0;
    if (i < n) {
        inc = d_off[i];                         // scan1's block-local inclusive
        prev = (tid == 0) ? 0 : d_off[i - 1];   // in-block neighbor
    }
    __syncthreads();                   // all reads done before any writes
    if (i < n) {
        int c = inc - prev;            // this node's count
        int e = prev + base;           // global exclusive offset
        d_off[i] = e;
        d_cur[i] = e;
        if (c > 0) {                   // warp-uniform address -> REDUX-aggregated
            int p = atomicAdd(&d_ntl, 1);
            d_tlist[p] = i;
        }
    }
    if (i == 0) d_off[n] = EDGES;      // sentinel
}

// ---------------- ppf compute (edge-parallel, unsorted; runs on side stream) ---------
__device__ __forceinline__ float angle3(float ax, float ay, float az,
                                        float bx, float by, float bz) {
    float cx = ay * bz - az * by;
    float cy = az * bx - ax * bz;
    float cz = ax * by - ay * bx;
    float cn = sqrtf(cx * cx + cy * cy + cz * cz);
    float d = ax * bx + ay * by + az * bz;
    return atan2f(cn, d);
}

__global__ void k_ppf(const int* __restrict__ col, const int* __restrict__ row,
                      const float* __restrict__ pos, const float* __restrict__ nor,
                      int E) {
    int i = blockIdx.x * blockDim.x + threadIdx.x;
    if (i >= E) return;
    int t = row[i];
    int s = col[i];
    float px = pos[3 * s]     - pos[3 * t];
    float py = pos[3 * s + 1] - pos[3 * t + 1];
    float pz = pos[3 * s + 2] - pos[3 * t + 2];
    float nsx = nor[3 * s], nsy = nor[3 * s + 1], nsz = nor[3 * s + 2];
    float ntx = nor[3 * t], nty = nor[3 * t + 1], ntz = nor[3 * t + 2];
    float f0 = sqrtf(px * px + py * py + pz * pz);
    float f1 = angle3(ntx, nty, ntz, px, py, pz);    // angle(n1, pseudo)
    float f2 = angle3(nsx, nsy, nsz, px, py, pz);    // angle(n0, pseudo)
    float f3 = angle3(ntx, nty, ntz, nsx, nsy, nsz); // angle(n1, n0)
    __half2 h01 = __floats2half2_rn(f0, f1);
    __half2 h23 = __floats2half2_rn(f2, f3);
    d_ppfu[i] = make_uint2(*(unsigned*)&h01, *(unsigned*)&h23);
}

// ---------------- scatter: pure permutation (ppf precomputed) -------------------------
__global__ void k_scatter(const int* __restrict__ col, const int* __restrict__ row, int E) {
    int i = blockIdx.x * blockDim.x + threadIdx.x;
    if (i < E) {
        int t = row[i];
        int p = atomicAdd(&d_cur[t], 1);
        d_src[p] = col[i];
        d_ppf[p] = d_ppfu[i];
    }
}

// ---------------- fused tf32 tensor-core GEMM: [64-row tile, K=64] x [64, 256] --------
// B[k][j] = (j<128) ? W[k][j] : W[64+k][j-128].
// cols 0..127 -> d_q (fp32, +bias), cols 128..255 -> d_pv (fp16).
#define A_STRIDE 68
#define B_STRIDE 264
#define GEMM_SMEM ((64 * A_STRIDE + 64 * B_STRIDE) * 4)

__device__ __forceinline__ unsigned tf32r(float f) {
    unsigned u;
    asm("cvt.rna.tf32.f32 %0, %1;" : "=r"(u) : "f"(f));
    return u;
}

__device__ __forceinline__ void mma_tf32(float& c0, float& c1, float& c2, float& c3,
                                         unsigned a0, unsigned a1, unsigned a2, unsigned a3,
                                         unsigned b0, unsigned b1) {
    asm volatile(
        "mma.sync.aligned.m16n8k8.row.col.f32.tf32.tf32.f32 "
        "{%0,%1,%2,%3}, {%4,%5,%6,%7}, {%8,%9}, {%0,%1,%2,%3};"
        : "+f"(c0), "+f"(c1), "+f"(c2), "+f"(c3)
        : "r"(a0), "r"(a1), "r"(a2), "r"(a3), "r"(b0), "r"(b1));
}

__global__ void __launch_bounds__(256)
k_gemm(const float* __restrict__ x, const float* __restrict__ Wm,
       const float* __restrict__ bv, int N) {
    extern __shared__ unsigned smem[];
    unsigned* As = smem;                     // [64][A_STRIDE]
    unsigned* Bs = smem + 64 * A_STRIDE;     // [64][B_STRIDE]
    int tid = threadIdx.x;
    int blk_row0 = blockIdx.x * 64;

    {   // A tile: 64 rows x 64 feats, tf32-rounded, row-major
        int r = tid >> 2;
        bool ok = (blk_row0 + r) < N;
        const float* xp = x + (size_t)(blk_row0 + r) * FEAT;
#pragma unroll
        for (int i = 0; i < 4; i++) {
            int c = (tid & 3) * 16 + i * 4;
            float4 v = ok ? *(const float4*)(xp + c) : make_float4(0.f, 0.f, 0.f, 0.f);
            unsigned* dst = &As[r * A_STRIDE + c];
            dst[0] = tf32r(v.x); dst[1] = tf32r(v.y);
            dst[2] = tf32r(v.z); dst[3] = tf32r(v.w);
        }
    }
    {   // B tile: 64 x 256 assembled from W rows [0:64) and [64:128)
#pragma unroll
        for (int it = 0; it < 16; it++) {
            int v = tid + 256 * it;          // 0..4095 float4 slots
            int k = v >> 6;
            int j0 = (v & 63) * 4;
            const float* src = (j0 < 128) ? (Wm + k * 128 + j0)
                                          : (Wm + (64 + k) * 128 + (j0 - 128));
            float4 w4 = *(const float4*)src;
            unsigned* dst = &Bs[k * B_STRIDE + j0];
            dst[0] = tf32r(w4.x); dst[1] = tf32r(w4.y);
            dst[2] = tf32r(w4.z); dst[3] = tf32r(w4.w);
        }
    }
    __syncthreads();

    int wid = tid >> 5;
    int lane = tid & 31;
    int row0 = (wid >> 2) * 32;      // 0 or 32
    int col0 = (wid & 3) * 64;       // 0,64,128,192
    int lr = lane >> 2;              // 0..7
    int lc = lane & 3;               // 0..3

    float c[2][8][4];
#pragma unroll
    for (int mt = 0; mt < 2; mt++)
#pragma unroll
        for (int nt = 0; nt < 8; nt++)
#pragma unroll
            for (int e = 0; e < 4; e++) c[mt][nt][e] = 0.f;

#pragma unroll
    for (int k0 = 0; k0 < 64; k0 += 8) {
        unsigned a[2][4], b[8][2];
#pragma unroll
        for (int mt = 0; mt < 2; mt++) {
            int ra = row0 + mt * 16 + lr;
            a[mt][0] = As[ra * A_STRIDE + k0 + lc];
            a[mt][1] = As[(ra + 8) * A_STRIDE + k0 + lc];
            a[mt][2] = As[ra * A_STRIDE + k0 + lc + 4];
            a[mt][3] = As[(ra + 8) * A_STRIDE + k0 + lc + 4];
        }
#pragma unroll
        for (int nt = 0; nt < 8; nt++) {
            int cb = col0 + nt * 8 + lr;
            b[nt][0] = Bs[(k0 + lc) * B_STRIDE + cb];
            b[nt][1] = Bs[(k0 + lc + 4) * B_STRIDE + cb];
        }
#pragma unroll
        for (int mt = 0; mt < 2; mt++)
#pragma unroll
            for (int nt = 0; nt < 8; nt++)
                mma_tf32(c[mt][nt][0], c[mt][nt][1], c[mt][nt][2], c[mt][nt][3],
                         a[mt][0], a[mt][1], a[mt][2], a[mt][3],
                         b[nt][0], b[nt][1]);
    }

    bool is_q = (col0 < 128);
#pragma unroll
    for (int mt = 0; mt < 2; mt++) {
        int r_lo = blk_row0 + row0 + mt * 16 + lr;
        int r_hi = r_lo + 8;
#pragma unroll
        for (int nt = 0; nt < 8; nt++) {
            int cc = col0 + nt * 8 + 2 * lc;
            if (is_q) {
                float2 bb = *(const float2*)&bv[cc];
                if (r_lo < N)
                    *(float2*)&d_q[(size_t)r_lo * 128 + cc] =
                        make_float2(c[mt][nt][0] + bb.x, c[mt][nt][1] + bb.y);
                if (r_hi < N)
                    *(float2*)&d_q[(size_t)r_hi * 128 + cc] =
                        make_float2(c[mt][nt][2] + bb.x, c[mt][nt][3] + bb.y);
            } else {
                int cp = cc - 128;
                if (r_lo < N) {
                    __half2 h = __floats2half2_rn(c[mt][nt][0], c[mt][nt][1]);
                    *(unsigned*)&d_pv[(size_t)r_lo * 128 + cp] = *(unsigned*)&h;
                }
                if (r_hi < N) {
                    __half2 h = __floats2half2_rn(c[mt][nt][2], c[mt][nt][3]);
                    *(unsigned*)&d_pv[(size_t)r_hi * 128 + cp] = *(unsigned*)&h;
                }
            }
        }
    }
}

// ---------------- edge aggregation: one warp per ACTIVE target, 4-edge batches --------
__global__ void k_agg(const float* __restrict__ Wm) {
    int wg = (blockIdx.x * blockDim.x + threadIdx.x) >> 5;
    if (wg >= d_ntl) return;
    int w = d_tlist[wg];                 // cnt > 0 guaranteed
    int lane = threadIdx.x & 31;
    int start = d_off[w];
    int end = d_off[w + 1];
    int col = lane * 4;

    float4 w0f = *(const float4*)&Wm[128 * 128 + col];   // ppf weight rows
    float4 w1f = *(const float4*)&Wm[129 * 128 + col];
    float4 w2f = *(const float4*)&Wm[130 * 128 + col];
    float4 w3f = *(const float4*)&Wm[131 * 128 + col];
    __half2 w0a = __floats2half2_rn(w0f.x, w0f.y), w0b = __floats2half2_rn(w0f.z, w0f.w);
    __half2 w1a = __floats2half2_rn(w1f.x, w1f.y), w1b = __floats2half2_rn(w1f.z, w1f.w);
    __half2 w2a = __floats2half2_rn(w2f.x, w2f.y), w2b = __floats2half2_rn(w2f.z, w2f.w);
    __half2 w3a = __floats2half2_rn(w3f.x, w3f.y), w3b = __floats2half2_rn(w3f.z, w3f.w);

    const __half2 NEGINF = __half2half2(__ushort_as_half(0xFC00));
    __half2 m0 = NEGINF, m1 = NEGINF;

    for (int base = start; base < end; base += 32) {
        int j = base + lane;
        int s = 0;
        uint2 pf = make_uint2(0u, 0u);
        if (j < end) {
            s = d_src[j];           // coalesced
            pf = d_ppf[j];          // coalesced 8B
        }
        int c32 = end - base;
        if (c32 > 32) c32 = 32;
        int i = 0;
        // ---- 4-edge batches: shfl+LDG issued up front, then HFMA2 block ----
        for (; i + 4 <= c32; i += 4) {
            uint2 pvv[4];
            unsigned gx[4], gy[4];
#pragma unroll
            for (int u = 0; u < 4; u++) {
                int si = __shfl_sync(0xffffffffu, s, i + u);
                gx[u] = __shfl_sync(0xffffffffu, pf.x, i + u);
                gy[u] = __shfl_sync(0xffffffffu, pf.y, i + u);
                pvv[u] = *(const uint2*)&d_pv[(size_t)si * 128 + col];
            }
            __half2 z0[4], z1[4];
#pragma unroll
            for (int u = 0; u < 4; u++) {
                __half2 hx = *(__half2*)&gx[u];       // (f0, f1)
                __half2 hy = *(__half2*)&gy[u];       // (f2, f3)
                __half2 g0 = __low2half2(hx),  g1 = __high2half2(hx);
                __half2 g2 = __low2half2(hy),  g3 = __high2half2(hy);
                __half2 p01 = *(__half2*)&pvv[u].x;
                __half2 p23 = *(__half2*)&pvv[u].y;
                z0[u] = __hfma2(g0, w0a, p01);  z1[u] = __hfma2(g0, w0b, p23);
                z0[u] = __hfma2(g1, w1a, z0[u]); z1[u] = __hfma2(g1, w1b, z1[u]);
                z0[u] = __hfma2(g2, w2a, z0[u]); z1[u] = __hfma2(g2, w2b, z1[u]);
                z0[u] = __hfma2(g3, w3a, z0[u]); z1[u] = __hfma2(g3, w3b, z1[u]);
            }
            m0 = __hmax2(m0, __hmax2(__hmax2(z0[0], z0[1]), __hmax2(z0[2], z0[3])));
            m1 = __hmax2(m1, __hmax2(__hmax2(z1[0], z1[1]), __hmax2(z1[2], z1[3])));
        }
        // ---- remainder ----
        for (; i < c32; i++) {
            int si = __shfl_sync(0xffffffffu, s, i);
            unsigned hxu = __shfl_sync(0xffffffffu, pf.x, i);
            unsigned hyu = __shfl_sync(0xffffffffu, pf.y, i);
            uint2 hv = *(const uint2*)&d_pv[(size_t)si * 128 + col];
            __half2 hx = *(__half2*)&hxu;
            __half2 hy = *(__half2*)&hyu;
            __half2 g0 = __low2half2(hx),  g1 = __high2half2(hx);
            __half2 g2 = __low2half2(hy),  g3 = __high2half2(hy);
            __half2 p01 = *(__half2*)&hv.x;
            __half2 p23 = *(__half2*)&hv.y;
            __half2 z0 = __hfma2(g0, w0a, p01);
            __half2 z1 = __hfma2(g0, w0b, p23);
            z0 = __hfma2(g1, w1a, z0); z1 = __hfma2(g1, w1b, z1);
            z0 = __hfma2(g2, w2a, z0); z1 = __hfma2(g2, w2b, z1);
            z0 = __hfma2(g3, w3a, z0); z1 = __hfma2(g3, w3b, z1);
            m0 = __hmax2(m0, z0);
            m1 = __hmax2(m1, z1);
        }
    }
    float2 a = __half22float2(m0);
    float2 b = __half22float2(m1);
    float4 q = *(const float4*)&d_q[(size_t)w * 128 + col];
    float4 r;
    r.x = fmaxf(q.x + a.x, 0.f);
    r.y = fmaxf(q.y + a.y, 0.f);
    r.z = fmaxf(q.z + b.x, 0.f);
    r.w = fmaxf(q.w + b.y, 0.f);
    *(float4*)&d_agg[(size_t)w * 128 + col] = r;
}

// ---------------- gather: out[s] = agg[idx[s]] (0 if no edges), pos_out ----------------
__global__ void k_gather(const float* __restrict__ pos, const int* __restrict__ idx,
                         float* __restrict__ out, int S) {
    int s = blockIdx.x;
    int h = threadIdx.x;  // 128
    int t = idx[s];
    bool has = d_off[t + 1] > d_off[t];
    float v = has ? d_agg[(size_t)t * 128 + h] : 0.f;
    out[(size_t)s * 128 + h] = v;
    if (h < 3) out[(size_t)S * 128 + (size_t)s * 3 + h] = pos[3 * t + h];
}

// ---------------- launch (gemm+ppf on side stream || sort chain) ----------------------
extern "C" void kernel_launch(void* const* d_in, const int* in_sizes, int n_in,
                              void* d_out, int out_size) {
    const float *x = 0, *pos = 0, *nor = 0, *Wm = 0, *bv = 0;
    const int *edge = 0, *idx = 0;
    for (int i = 0; i < n_in; i++) {
        int sz = in_sizes[i];
        if (sz == NODES * FEAT) x = (const float*)d_in[i];
        else if (sz == NODES * 3) { if (!pos) pos = (const float*)d_in[i]; else nor = (const float*)d_in[i]; }
        else if (sz == (2 * FEAT + 4) * HID) Wm = (const float*)d_in[i];
        else if (sz == HID) bv = (const float*)d_in[i];
        else if (sz == 2 * EDGES) edge = (const int*)d_in[i];
        else if (sz == SAMP) idx = (const int*)d_in[i];
    }
    const int* ecol = edge;          // e0 (sources)
    const int* erow = edge + EDGES;  // e1 (targets)

    static cudaStream_t sB = 0;
    static cudaEvent_t eFork = 0, ePv = 0, ePpf = 0;
    if (!sB) {
        cudaStreamCreateWithFlags(&sB, cudaStreamNonBlocking);
        cudaEventCreateWithFlags(&eFork, cudaEventDisableTiming);
        cudaEventCreateWithFlags(&ePv,   cudaEventDisableTiming);
        cudaEventCreateWithFlags(&ePpf,  cudaEventDisableTiming);
        cudaFuncSetAttribute(k_gemm, cudaFuncAttributeMaxDynamicSharedMemorySize, GEMM_SMEM);
    }

    // fork: tensor-core gemm + ppf compute on sB, independent of the sort chain
    cudaEventRecord(eFork, 0);
    cudaStreamWaitEvent(sB, eFork, 0);
    k_gemm<<<(NODES + 63) / 64, 256, GEMM_SMEM, sB>>>(x, Wm, bv, NODES);
    cudaEventRecord(ePv, sB);
    k_ppf<<<(EDGES + 255) / 256, 256, 0, sB>>>(ecol, erow, pos, nor, EDGES);
    cudaEventRecord(ePpf, sB);

    // sort chain on the main stream (zero_cnt removed; scan1 self-cleans)
    k_hist<<<(EDGES + 255) / 256, 256>>>(erow, EDGES);
    k_scan1<<<(NODES + 1023) / 1024, 1024>>>(NODES);
    k_scan3<<<(NODES + 1023) / 1024, 1024>>>(NODES);
    cudaStreamWaitEvent(0, ePpf, 0);   // scatter permutes d_ppfu
    k_scatter<<<(EDGES + 255) / 256, 256>>>(ecol, erow, EDGES);

    // join: agg needs scatter (main) + gemm (sB); one warp per active target
    cudaStreamWaitEvent(0, ePv, 0);
    k_agg<<<(SAMP + 7) / 8, 256>>>(Wm);
    k_gather<<<SAMP, 128>>>(pos, idx, (float*)d_out, SAMP);
}